// round 1
// baseline (speedup 1.0000x reference)
#include <cuda_runtime.h>

#define BATCH  4096
#define IDIM   1024
#define BOND   32
#define ODIM   512
#define NCHUNK 64
#define CHUNK  16   // NCHUNK * CHUNK == IDIM

// Scratch (no allocation allowed): chunk products and the final weight vector.
__device__ float g_P[NCHUNK][BOND * BOND];
__device__ float g_w[ODIM];

// ---------------------------------------------------------------------------
// Kernel 1: each block computes the ordered product of CHUNK consecutive
// 32x32 cores:  P_c = C_{16c} @ C_{16c+1} @ ... @ C_{16c+15}
// 1024 threads = one (j,k) element each. smem double-buffer + 1-deep LDG
// prefetch hides L2 latency behind the FMA chain.
// ---------------------------------------------------------------------------
__global__ __launch_bounds__(1024) void mps_chunk_kernel(const float* __restrict__ cores) {
    __shared__ float sA[BOND][BOND + 1];
    __shared__ float sB[2][BOND][BOND + 1];

    const int c   = blockIdx.x;
    const int tid = threadIdx.x;
    const int j   = tid >> 5;
    const int k   = tid & 31;

    const float* base = cores + (size_t)c * CHUNK * (BOND * BOND);

    sA[j][k]  = base[tid];                       // A = C_{16c}
    float pre = base[BOND * BOND + tid];         // prefetch C_{16c+1}
    __syncthreads();

    #pragma unroll
    for (int i = 1; i < CHUNK; ++i) {
        sB[i & 1][j][k] = pre;
        if (i + 1 < CHUNK) pre = base[(i + 1) * (BOND * BOND) + tid];
        __syncthreads();                         // sB ready; prior sA stores visible

        float a0 = 0.f, a1 = 0.f, a2 = 0.f, a3 = 0.f;
        #pragma unroll
        for (int l = 0; l < 8; ++l) {
            a0 = fmaf(sA[j][l],      sB[i & 1][l][k],      a0);
            a1 = fmaf(sA[j][l + 8],  sB[i & 1][l + 8][k],  a1);
            a2 = fmaf(sA[j][l + 16], sB[i & 1][l + 16][k], a2);
            a3 = fmaf(sA[j][l + 24], sB[i & 1][l + 24][k], a3);
        }
        __syncthreads();                         // all reads of sA done
        sA[j][k] = (a0 + a1) + (a2 + a3);
    }
    __syncthreads();
    g_P[c][tid] = sA[j][k];
}

// ---------------------------------------------------------------------------
// Kernel 2: single block. Warp 0 chains v = ones @ P_0 @ ... @ P_63 with
// register double-buffered loads of the next chunk column (latency hidden).
// Then all 512 threads compute w = v @ projection.
// ---------------------------------------------------------------------------
__global__ __launch_bounds__(512) void mps_combine_kernel(const float* __restrict__ proj) {
    __shared__ float sv[BOND];
    const int tid = threadIdx.x;

    if (tid < 32) {
        const int k = tid;
        float v = 1.0f;

        float cur[32], nxt[32];
        #pragma unroll
        for (int j = 0; j < 32; ++j) cur[j] = g_P[0][j * 32 + k];

        #pragma unroll 1
        for (int c = 0; c < NCHUNK; ++c) {
            // prefetch next chunk's column k (independent of v-chain)
            if (c + 1 < NCHUNK) {
                #pragma unroll
                for (int j = 0; j < 32; ++j) nxt[j] = g_P[c + 1][j * 32 + k];
            }
            float a0 = 0.f, a1 = 0.f, a2 = 0.f, a3 = 0.f;
            #pragma unroll
            for (int j = 0; j < 8; ++j) {
                a0 = fmaf(__shfl_sync(0xffffffffu, v, j),      cur[j],      a0);
                a1 = fmaf(__shfl_sync(0xffffffffu, v, j + 8),  cur[j + 8],  a1);
                a2 = fmaf(__shfl_sync(0xffffffffu, v, j + 16), cur[j + 16], a2);
                a3 = fmaf(__shfl_sync(0xffffffffu, v, j + 24), cur[j + 24], a3);
            }
            v = (a0 + a1) + (a2 + a3);
            #pragma unroll
            for (int j = 0; j < 32; ++j) cur[j] = nxt[j];
        }
        sv[k] = v;
    }
    __syncthreads();

    float acc = 0.f;
    #pragma unroll
    for (int j = 0; j < BOND; ++j)
        acc = fmaf(sv[j], proj[j * ODIM + tid], acc);
    g_w[tid] = acc;
}

// ---------------------------------------------------------------------------
// Kernel 3: per batch row b, s_b = prod(inputs[b,:]) via float4 loads +
// warp/smem multiply-reduce, then out[b,:] = s_b * w + bias. Pure bandwidth.
// ---------------------------------------------------------------------------
__global__ __launch_bounds__(256) void mps_output_kernel(const float* __restrict__ inputs,
                                                         const float* __restrict__ bias,
                                                         float* __restrict__ out) {
    const int b   = blockIdx.x;
    const int tid = threadIdx.x;

    const float4* row = (const float4*)(inputs + (size_t)b * IDIM);
    float4 r = row[tid];                               // 256 threads * 4 = 1024 elems
    float  p = (r.x * r.y) * (r.z * r.w);

    #pragma unroll
    for (int off = 16; off; off >>= 1)
        p *= __shfl_xor_sync(0xffffffffu, p, off);

    __shared__ float swp[8];
    if ((tid & 31) == 0) swp[tid >> 5] = p;
    __syncthreads();

    const float s = ((swp[0] * swp[1]) * (swp[2] * swp[3])) *
                    ((swp[4] * swp[5]) * (swp[6] * swp[7]));

    float* o = out + (size_t)b * ODIM;
    o[tid]       = fmaf(s, g_w[tid],       bias[tid]);
    o[tid + 256] = fmaf(s, g_w[tid + 256], bias[tid + 256]);
}

// ---------------------------------------------------------------------------
extern "C" void kernel_launch(void* const* d_in, const int* in_sizes, int n_in,
                              void* d_out, int out_size) {
    const float* inputs = (const float*)d_in[0];
    const float* cores  = (const float*)d_in[1];
    const float* proj   = (const float*)d_in[2];
    const float* bias   = (const float*)d_in[3];
    float* out = (float*)d_out;

    mps_chunk_kernel  <<<NCHUNK, 1024>>>(cores);
    mps_combine_kernel<<<1, 512>>>(proj);
    mps_output_kernel <<<BATCH, 256>>>(inputs, bias, out);
}

// round 3
// speedup vs baseline: 1.2598x; 1.2598x over previous
#include <cuda_runtime.h>

#define BATCH  4096
#define IDIM   1024
#define BOND   32
#define ODIM   512

// Tree: 1024 cores -> 256 products of 4 -> 64 products of 4 -> 64-step vector chain
#define NP1 256
#define NP2 64

__device__ float g_P1[NP1 * BOND * BOND];   // 1 MB scratch
__device__ float g_P2[NP2 * BOND * BOND];   // 256 KB scratch
__device__ float g_w[ODIM];

// ---------------------------------------------------------------------------
// Transposed store of a float4 covering elements 4t..4t+3 of a 32x32 matrix
// into Bt (pitch 33). Conflict-free: bank = (4m+q) mod 32 is a permutation.
// ---------------------------------------------------------------------------
__device__ __forceinline__ void transpose_store(float4 v, float* Bt, int t) {
    const int j  = t >> 3;          // row of source matrix
    const int k0 = (t & 7) * 4;     // first column of the 4
    Bt[(k0 + 0) * 33 + j] = v.x;
    Bt[(k0 + 1) * 33 + j] = v.y;
    Bt[(k0 + 2) * 33 + j] = v.z;
    Bt[(k0 + 3) * 33 + j] = v.w;
}

// ---------------------------------------------------------------------------
// Block = ordered product of 4 consecutive 32x32 matrices from src.
// 256 threads: warp w owns rows 4w..4w+3, lane = output column.
// A rows read as uniform (broadcast) LDS.128; B columns read stride-1 from
// the transposed buffer. FMA-pipe bound (~512 cyc/matmul), depth 3.
// ---------------------------------------------------------------------------
__global__ __launch_bounds__(256) void mps_prod4_kernel(const float* __restrict__ src,
                                                        float* __restrict__ dst) {
    __shared__ float sA[BOND * BOND];        // running product, pitch 32
    __shared__ float sBt[2][BOND * 33];      // next core, transposed, pitch 33

    const int t    = threadIdx.x;
    const int w    = t >> 5;
    const int lane = t & 31;
    const float* base = src + (size_t)blockIdx.x * (4 * BOND * BOND);

    ((float4*)sA)[t] = ((const float4*)base)[t];                       // core 0 as rows
    transpose_store(((const float4*)(base + BOND * BOND))[t], sBt[1], t); // core 1 ^T
    __syncthreads();

    float acc0 = 0.f, acc1 = 0.f, acc2 = 0.f, acc3 = 0.f;

    #pragma unroll
    for (int s = 1; s < 4; ++s) {
        float4 pre;
        if (s + 1 < 4) pre = ((const float4*)(base + (s + 1) * BOND * BOND))[t];

        const float* Bt = sBt[s & 1];
        acc0 = acc1 = acc2 = acc3 = 0.f;

        #pragma unroll
        for (int l4 = 0; l4 < 8; ++l4) {
            const float4 a0 = *(const float4*)(sA + (4 * w + 0) * 32 + 4 * l4);
            const float4 a1 = *(const float4*)(sA + (4 * w + 1) * 32 + 4 * l4);
            const float4 a2 = *(const float4*)(sA + (4 * w + 2) * 32 + 4 * l4);
            const float4 a3 = *(const float4*)(sA + (4 * w + 3) * 32 + 4 * l4);
            const float b0 = Bt[lane * 33 + 4 * l4 + 0];
            const float b1 = Bt[lane * 33 + 4 * l4 + 1];
            const float b2 = Bt[lane * 33 + 4 * l4 + 2];
            const float b3 = Bt[lane * 33 + 4 * l4 + 3];

            acc0 = fmaf(a0.x, b0, acc0); acc0 = fmaf(a0.y, b1, acc0);
            acc0 = fmaf(a0.z, b2, acc0); acc0 = fmaf(a0.w, b3, acc0);
            acc1 = fmaf(a1.x, b0, acc1); acc1 = fmaf(a1.y, b1, acc1);
            acc1 = fmaf(a1.z, b2, acc1); acc1 = fmaf(a1.w, b3, acc1);
            acc2 = fmaf(a2.x, b0, acc2); acc2 = fmaf(a2.y, b1, acc2);
            acc2 = fmaf(a2.z, b2, acc2); acc2 = fmaf(a2.w, b3, acc2);
            acc3 = fmaf(a3.x, b0, acc3); acc3 = fmaf(a3.y, b1, acc3);
            acc3 = fmaf(a3.z, b2, acc3); acc3 = fmaf(a3.w, b3, acc3);
        }
        __syncthreads();                          // all reads of sA / sBt done
        if (s < 3) {
            sA[(4 * w + 0) * 32 + lane] = acc0;
            sA[(4 * w + 1) * 32 + lane] = acc1;
            sA[(4 * w + 2) * 32 + lane] = acc2;
            sA[(4 * w + 3) * 32 + lane] = acc3;
            transpose_store(pre, sBt[(s + 1) & 1], t);
            __syncthreads();
        }
    }

    float* d = dst + (size_t)blockIdx.x * (BOND * BOND);
    d[(4 * w + 0) * 32 + lane] = acc0;
    d[(4 * w + 1) * 32 + lane] = acc1;
    d[(4 * w + 2) * 32 + lane] = acc2;
    d[(4 * w + 3) * 32 + lane] = acc3;
}

// ---------------------------------------------------------------------------
// Combine: warp 0 chains v = ones @ P2_0 @ ... @ P2_63 with register
// double-buffered prefetch, then all 512 threads compute w = v @ projection.
// ---------------------------------------------------------------------------
__global__ __launch_bounds__(512) void mps_combine_kernel(const float* __restrict__ proj) {
    __shared__ float sv[BOND];
    const int tid = threadIdx.x;

    if (tid < 32) {
        const int k = tid;
        float v = 1.0f;

        float cur[32], nxt[32];
        #pragma unroll
        for (int j = 0; j < 32; ++j) cur[j] = g_P2[j * 32 + k];

        #pragma unroll 1
        for (int c = 0; c < NP2; ++c) {
            if (c + 1 < NP2) {
                #pragma unroll
                for (int j = 0; j < 32; ++j) nxt[j] = g_P2[(c + 1) * 1024 + j * 32 + k];
            }
            float a0 = 0.f, a1 = 0.f, a2 = 0.f, a3 = 0.f;
            #pragma unroll
            for (int j = 0; j < 8; ++j) {
                a0 = fmaf(__shfl_sync(0xffffffffu, v, j),      cur[j],      a0);
                a1 = fmaf(__shfl_sync(0xffffffffu, v, j + 8),  cur[j + 8],  a1);
                a2 = fmaf(__shfl_sync(0xffffffffu, v, j + 16), cur[j + 16], a2);
                a3 = fmaf(__shfl_sync(0xffffffffu, v, j + 24), cur[j + 24], a3);
            }
            v = (a0 + a1) + (a2 + a3);
            #pragma unroll
            for (int j = 0; j < 32; ++j) cur[j] = nxt[j];
        }
        sv[k] = v;
    }
    __syncthreads();

    float acc = 0.f;
    #pragma unroll
    for (int j = 0; j < BOND; ++j)
        acc = fmaf(sv[j], proj[j * ODIM + tid], acc);
    g_w[tid] = acc;
}

// ---------------------------------------------------------------------------
// Output: s_b = prod(inputs[b,:]); out[b,:] = s_b * w + bias. Bandwidth-bound.
// ---------------------------------------------------------------------------
__global__ __launch_bounds__(256) void mps_output_kernel(const float* __restrict__ inputs,
                                                         const float* __restrict__ bias,
                                                         float* __restrict__ out) {
    const int b   = blockIdx.x;
    const int tid = threadIdx.x;

    const float4* row = (const float4*)(inputs + (size_t)b * IDIM);
    float4 r = row[tid];
    float  p = (r.x * r.y) * (r.z * r.w);

    #pragma unroll
    for (int off = 16; off; off >>= 1)
        p *= __shfl_xor_sync(0xffffffffu, p, off);

    __shared__ float swp[8];
    if ((tid & 31) == 0) swp[tid >> 5] = p;
    __syncthreads();

    const float s = ((swp[0] * swp[1]) * (swp[2] * swp[3])) *
                    ((swp[4] * swp[5]) * (swp[6] * swp[7]));

    float* o = out + (size_t)b * ODIM;
    o[tid]       = fmaf(s, g_w[tid],       bias[tid]);
    o[tid + 256] = fmaf(s, g_w[tid + 256], bias[tid + 256]);
}

// ---------------------------------------------------------------------------
extern "C" void kernel_launch(void* const* d_in, const int* in_sizes, int n_in,
                              void* d_out, int out_size) {
    const float* inputs = (const float*)d_in[0];
    const float* cores  = (const float*)d_in[1];
    const float* proj   = (const float*)d_in[2];
    const float* bias   = (const float*)d_in[3];
    float* out = (float*)d_out;

    float* p1; cudaGetSymbolAddress((void**)&p1, g_P1);
    float* p2; cudaGetSymbolAddress((void**)&p2, g_P2);

    mps_prod4_kernel  <<<NP1, 256>>>(cores, p1);   // 1024 cores -> 256 products
    mps_prod4_kernel  <<<NP2, 256>>>(p1, p2);      // 256 -> 64
    mps_combine_kernel<<<1, 512>>>(proj);          // 64-chain + projection
    mps_output_kernel <<<BATCH, 256>>>(inputs, bias, out);
}

// round 6
// speedup vs baseline: 2.2215x; 1.7634x over previous
#include <cuda_runtime.h>

#define BATCH  4096
#define IDIM   1024
#define BOND   32
#define ODIM   512

// Tree: 1024 cores -> 256 -> 64 -> 16 (prod4 x3), then 16-step vector chain.
#define NP1 256
#define NP2 64
#define NP3 16

__device__ __align__(16) float g_P1[NP1 * BOND * BOND];
__device__ __align__(16) float g_P2[NP2 * BOND * BOND];
__device__ __align__(16) float g_P3[NP3 * BOND * BOND];
__device__ __align__(16) float g_w[ODIM];

// ---------------------------------------------------------------------------
// Transposed store of a float4 covering elements 4t..4t+3 of a 32x32 matrix
// into Bt (pitch 33). Conflict-free.
// ---------------------------------------------------------------------------
__device__ __forceinline__ void transpose_store(float4 v, float* Bt, int t) {
    const int j  = t >> 3;
    const int k0 = (t & 7) * 4;
    Bt[(k0 + 0) * 33 + j] = v.x;
    Bt[(k0 + 1) * 33 + j] = v.y;
    Bt[(k0 + 2) * 33 + j] = v.z;
    Bt[(k0 + 3) * 33 + j] = v.w;
}

// ---------------------------------------------------------------------------
// Block = ordered product of 4 consecutive 32x32 matrices (depth 3).
// Warp w owns rows 4w..4w+3; lane = output column. A rows are uniform
// broadcast LDS.128; B columns read stride-1 from transposed buffer.
// ---------------------------------------------------------------------------
__global__ __launch_bounds__(256) void mps_prod4_kernel(const float* __restrict__ src,
                                                        float* __restrict__ dst) {
    __shared__ float sA[BOND * BOND];
    __shared__ float sBt[2][BOND * 33];

    const int t    = threadIdx.x;
    const int w    = t >> 5;
    const int lane = t & 31;
    const float* base = src + (size_t)blockIdx.x * (4 * BOND * BOND);

    ((float4*)sA)[t] = ((const float4*)base)[t];
    transpose_store(((const float4*)(base + BOND * BOND))[t], sBt[1], t);
    __syncthreads();

    float acc0 = 0.f, acc1 = 0.f, acc2 = 0.f, acc3 = 0.f;

    #pragma unroll
    for (int s = 1; s < 4; ++s) {
        float4 pre;
        if (s + 1 < 4) pre = ((const float4*)(base + (s + 1) * BOND * BOND))[t];

        const float* Bt = sBt[s & 1];
        acc0 = acc1 = acc2 = acc3 = 0.f;

        #pragma unroll
        for (int l4 = 0; l4 < 8; ++l4) {
            const float4 a0 = *(const float4*)(sA + (4 * w + 0) * 32 + 4 * l4);
            const float4 a1 = *(const float4*)(sA + (4 * w + 1) * 32 + 4 * l4);
            const float4 a2 = *(const float4*)(sA + (4 * w + 2) * 32 + 4 * l4);
            const float4 a3 = *(const float4*)(sA + (4 * w + 3) * 32 + 4 * l4);
            const float b0 = Bt[lane * 33 + 4 * l4 + 0];
            const float b1 = Bt[lane * 33 + 4 * l4 + 1];
            const float b2 = Bt[lane * 33 + 4 * l4 + 2];
            const float b3 = Bt[lane * 33 + 4 * l4 + 3];

            acc0 = fmaf(a0.x, b0, acc0); acc0 = fmaf(a0.y, b1, acc0);
            acc0 = fmaf(a0.z, b2, acc0); acc0 = fmaf(a0.w, b3, acc0);
            acc1 = fmaf(a1.x, b0, acc1); acc1 = fmaf(a1.y, b1, acc1);
            acc1 = fmaf(a1.z, b2, acc1); acc1 = fmaf(a1.w, b3, acc1);
            acc2 = fmaf(a2.x, b0, acc2); acc2 = fmaf(a2.y, b1, acc2);
            acc2 = fmaf(a2.z, b2, acc2); acc2 = fmaf(a2.w, b3, acc2);
            acc3 = fmaf(a3.x, b0, acc3); acc3 = fmaf(a3.y, b1, acc3);
            acc3 = fmaf(a3.z, b2, acc3); acc3 = fmaf(a3.w, b3, acc3);
        }
        __syncthreads();
        if (s < 3) {
            sA[(4 * w + 0) * 32 + lane] = acc0;
            sA[(4 * w + 1) * 32 + lane] = acc1;
            sA[(4 * w + 2) * 32 + lane] = acc2;
            sA[(4 * w + 3) * 32 + lane] = acc3;
            transpose_store(pre, sBt[(s + 1) & 1], t);
            __syncthreads();
        }
    }

    float* d = dst + (size_t)blockIdx.x * (BOND * BOND);
    d[(4 * w + 0) * 32 + lane] = acc0;
    d[(4 * w + 1) * 32 + lane] = acc1;
    d[(4 * w + 2) * 32 + lane] = acc2;
    d[(4 * w + 3) * 32 + lane] = acc3;
}

// ---------------------------------------------------------------------------
// Combine: warp 0 chains v = ones @ P3_0 @ ... @ P3_15 with 3-deep register
// prefetch (fully unrolled -> no copies, arrays stay in registers). Then all
// 512 threads compute w = v @ projection.
// ---------------------------------------------------------------------------
__global__ __launch_bounds__(512) void mps_combine_kernel(const float* __restrict__ proj) {
    __shared__ float sv[BOND];
    const int tid = threadIdx.x;

    if (tid < 32) {
        const int k = tid;
        float v = 1.0f;

        float cur[32], n1[32], n2[32];
        #pragma unroll
        for (int j = 0; j < 32; ++j) cur[j] = g_P3[j * 32 + k];
        #pragma unroll
        for (int j = 0; j < 32; ++j) n1[j]  = g_P3[1024 + j * 32 + k];
        #pragma unroll
        for (int j = 0; j < 32; ++j) n2[j]  = g_P3[2048 + j * 32 + k];

        #pragma unroll
        for (int c = 0; c < NP3; ++c) {
            float a0 = 0.f, a1 = 0.f, a2 = 0.f, a3 = 0.f;
            #pragma unroll
            for (int j = 0; j < 8; ++j) {
                a0 = fmaf(__shfl_sync(0xffffffffu, v, j),      cur[j],      a0);
                a1 = fmaf(__shfl_sync(0xffffffffu, v, j + 8),  cur[j + 8],  a1);
                a2 = fmaf(__shfl_sync(0xffffffffu, v, j + 16), cur[j + 16], a2);
                a3 = fmaf(__shfl_sync(0xffffffffu, v, j + 24), cur[j + 24], a3);
            }
            #pragma unroll
            for (int j = 0; j < 32; ++j) cur[j] = n1[j];
            #pragma unroll
            for (int j = 0; j < 32; ++j) n1[j] = n2[j];
            if (c + 3 < NP3) {
                #pragma unroll
                for (int j = 0; j < 32; ++j) n2[j] = g_P3[(c + 3) * 1024 + j * 32 + k];
            }
            v = (a0 + a1) + (a2 + a3);
        }
        sv[k] = v;
    }
    __syncthreads();

    float acc = 0.f;
    #pragma unroll
    for (int j = 0; j < BOND; ++j)
        acc = fmaf(sv[j], proj[j * ODIM + tid], acc);
    g_w[tid] = acc;
}

// ---------------------------------------------------------------------------
// Output: one warp per batch row, 8 rows per block. No smem, no barriers.
// 8 independent LDG.128 per lane (MLP=8), warp multiply-reduce, float4 stores.
// ---------------------------------------------------------------------------
__global__ __launch_bounds__(256) void mps_output_kernel(const float* __restrict__ inputs,
                                                         const float* __restrict__ bias,
                                                         float* __restrict__ out) {
    const int lane = threadIdx.x & 31;
    const int b    = blockIdx.x * 8 + (threadIdx.x >> 5);

    const float4* row = (const float4*)(inputs + (size_t)b * IDIM);
    float4 r[8];
    #pragma unroll
    for (int i = 0; i < 8; ++i) r[i] = row[lane + 32 * i];

    float p0 = (r[0].x * r[0].y) * (r[0].z * r[0].w);
    float p1 = (r[1].x * r[1].y) * (r[1].z * r[1].w);
    float p2 = (r[2].x * r[2].y) * (r[2].z * r[2].w);
    float p3 = (r[3].x * r[3].y) * (r[3].z * r[3].w);
    float p4 = (r[4].x * r[4].y) * (r[4].z * r[4].w);
    float p5 = (r[5].x * r[5].y) * (r[5].z * r[5].w);
    float p6 = (r[6].x * r[6].y) * (r[6].z * r[6].w);
    float p7 = (r[7].x * r[7].y) * (r[7].z * r[7].w);
    float p  = ((p0 * p1) * (p2 * p3)) * ((p4 * p5) * (p6 * p7));

    #pragma unroll
    for (int off = 16; off; off >>= 1)
        p *= __shfl_xor_sync(0xffffffffu, p, off);

    const float4* w4 = (const float4*)g_w;
    const float4* b4 = (const float4*)bias;
    float4*       o4 = (float4*)(out + (size_t)b * ODIM);

    #pragma unroll
    for (int i = 0; i < 4; ++i) {
        const float4 wv = w4[lane + 32 * i];
        const float4 bv = b4[lane + 32 * i];
        float4 ov;
        ov.x = fmaf(p, wv.x, bv.x);
        ov.y = fmaf(p, wv.y, bv.y);
        ov.z = fmaf(p, wv.z, bv.z);
        ov.w = fmaf(p, wv.w, bv.w);
        o4[lane + 32 * i] = ov;
    }
}

// ---------------------------------------------------------------------------
extern "C" void kernel_launch(void* const* d_in, const int* in_sizes, int n_in,
                              void* d_out, int out_size) {
    const float* inputs = (const float*)d_in[0];
    const float* cores  = (const float*)d_in[1];
    const float* proj   = (const float*)d_in[2];
    const float* bias   = (const float*)d_in[3];
    float* out = (float*)d_out;

    float* p1; cudaGetSymbolAddress((void**)&p1, g_P1);
    float* p2; cudaGetSymbolAddress((void**)&p2, g_P2);
    float* p3; cudaGetSymbolAddress((void**)&p3, g_P3);

    mps_prod4_kernel  <<<NP1, 256>>>(cores, p1);   // 1024 -> 256
    mps_prod4_kernel  <<<NP2, 256>>>(p1, p2);      // 256  -> 64
    mps_prod4_kernel  <<<NP3, 256>>>(p2, p3);      // 64   -> 16
    mps_combine_kernel<<<1, 512>>>(proj);          // 16-chain + projection
    mps_output_kernel <<<BATCH / 8, 256>>>(inputs, bias, out);
}

// round 9
// speedup vs baseline: 2.2462x; 1.0111x over previous
#include <cuda_runtime.h>

#define BATCH  4096
#define IDIM   1024
#define BOND   32
#define ODIM   512

// Tree: 1024 cores -> 256 -> 64 -> 16 (prod4 x3), then 16-step chain in smem.
#define NP1 256
#define NP2 64
#define NP3 16

__device__ __align__(16) float g_P1[NP1 * BOND * BOND];
__device__ __align__(16) float g_P2[NP2 * BOND * BOND];
__device__ __align__(16) float g_P3[NP3 * BOND * BOND];
__device__ __align__(16) float g_w[ODIM];

// ---------------------------------------------------------------------------
// Transposed store of a float4 covering elements 4t..4t+3 of a 32x32 matrix
// into Bt (pitch 33). Conflict-free.
// ---------------------------------------------------------------------------
__device__ __forceinline__ void transpose_store(float4 v, float* Bt, int t) {
    const int j  = t >> 3;
    const int k0 = (t & 7) * 4;
    Bt[(k0 + 0) * 33 + j] = v.x;
    Bt[(k0 + 1) * 33 + j] = v.y;
    Bt[(k0 + 2) * 33 + j] = v.z;
    Bt[(k0 + 3) * 33 + j] = v.w;
}

// ---------------------------------------------------------------------------
// Block = ordered product of 4 consecutive 32x32 matrices (depth 3).
// Warp w owns rows 4w..4w+3; lane = output column. A rows are uniform
// broadcast LDS.128; B columns read stride-1 from transposed buffer.
// ---------------------------------------------------------------------------
__global__ __launch_bounds__(256) void mps_prod4_kernel(const float* __restrict__ src,
                                                        float* __restrict__ dst) {
    __shared__ float sA[BOND * BOND];
    __shared__ float sBt[2][BOND * 33];

    const int t    = threadIdx.x;
    const int w    = t >> 5;
    const int lane = t & 31;
    const float* base = src + (size_t)blockIdx.x * (4 * BOND * BOND);

    ((float4*)sA)[t] = ((const float4*)base)[t];
    transpose_store(((const float4*)(base + BOND * BOND))[t], sBt[1], t);
    __syncthreads();

    float acc0 = 0.f, acc1 = 0.f, acc2 = 0.f, acc3 = 0.f;

    #pragma unroll
    for (int s = 1; s < 4; ++s) {
        float4 pre;
        if (s + 1 < 4) pre = ((const float4*)(base + (s + 1) * BOND * BOND))[t];

        const float* Bt = sBt[s & 1];
        acc0 = acc1 = acc2 = acc3 = 0.f;

        #pragma unroll
        for (int l4 = 0; l4 < 8; ++l4) {
            const float4 a0 = *(const float4*)(sA + (4 * w + 0) * 32 + 4 * l4);
            const float4 a1 = *(const float4*)(sA + (4 * w + 1) * 32 + 4 * l4);
            const float4 a2 = *(const float4*)(sA + (4 * w + 2) * 32 + 4 * l4);
            const float4 a3 = *(const float4*)(sA + (4 * w + 3) * 32 + 4 * l4);
            const float b0 = Bt[lane * 33 + 4 * l4 + 0];
            const float b1 = Bt[lane * 33 + 4 * l4 + 1];
            const float b2 = Bt[lane * 33 + 4 * l4 + 2];
            const float b3 = Bt[lane * 33 + 4 * l4 + 3];

            acc0 = fmaf(a0.x, b0, acc0); acc0 = fmaf(a0.y, b1, acc0);
            acc0 = fmaf(a0.z, b2, acc0); acc0 = fmaf(a0.w, b3, acc0);
            acc1 = fmaf(a1.x, b0, acc1); acc1 = fmaf(a1.y, b1, acc1);
            acc1 = fmaf(a1.z, b2, acc1); acc1 = fmaf(a1.w, b3, acc1);
            acc2 = fmaf(a2.x, b0, acc2); acc2 = fmaf(a2.y, b1, acc2);
            acc2 = fmaf(a2.z, b2, acc2); acc2 = fmaf(a2.w, b3, acc2);
            acc3 = fmaf(a3.x, b0, acc3); acc3 = fmaf(a3.y, b1, acc3);
            acc3 = fmaf(a3.z, b2, acc3); acc3 = fmaf(a3.w, b3, acc3);
        }
        __syncthreads();
        if (s < 3) {
            sA[(4 * w + 0) * 32 + lane] = acc0;
            sA[(4 * w + 1) * 32 + lane] = acc1;
            sA[(4 * w + 2) * 32 + lane] = acc2;
            sA[(4 * w + 3) * 32 + lane] = acc3;
            transpose_store(pre, sBt[(s + 1) & 1], t);
            __syncthreads();
        }
    }

    float* d = dst + (size_t)blockIdx.x * (BOND * BOND);
    d[(4 * w + 0) * 32 + lane] = acc0;
    d[(4 * w + 1) * 32 + lane] = acc1;
    d[(4 * w + 2) * 32 + lane] = acc2;
    d[(4 * w + 3) * 32 + lane] = acc3;
}

// ---------------------------------------------------------------------------
// Combine: stage all 16 P3 matrices into 64KB dynamic smem (bulk coalesced
// load: 512 threads x 8 float4 = 4096 float4 = 64KB), warp 0 chains
// v = ones @ P3_0 @ ... @ P3_15 from smem (broadcast LDS, no register
// arrays -> no spills). Projection columns are loaded into registers by all
// 512 threads BEFORE the barrier so their latency hides under the chain.
// Then w = v @ projection.
// ---------------------------------------------------------------------------
__global__ __launch_bounds__(512) void mps_combine_kernel(const float* __restrict__ proj) {
    extern __shared__ float sP[];            // 16 * 1024 floats = 64 KB
    __shared__ float sv[BOND];

    const int tid  = threadIdx.x;
    const int lane = tid & 31;

    // Independent work first: each thread's projection column -> registers.
    float pr[BOND];
    #pragma unroll
    for (int j = 0; j < BOND; ++j) pr[j] = proj[j * ODIM + tid];

    // Bulk stage P3: 512 threads * 8 float4 = 4096 float4 = 16384 floats.
    const float4* g4 = (const float4*)g_P3;
    float4*       s4 = (float4*)sP;
    #pragma unroll
    for (int i = 0; i < 8; ++i) s4[tid + 512 * i] = g4[tid + 512 * i];
    __syncthreads();

    if (tid < 32) {
        float v = 1.0f;
        #pragma unroll
        for (int c = 0; c < NP3; ++c) {
            const float* P = sP + c * 1024;
            float a0 = 0.f, a1 = 0.f, a2 = 0.f, a3 = 0.f;
            #pragma unroll
            for (int j = 0; j < 8; ++j) {
                a0 = fmaf(__shfl_sync(0xffffffffu, v, j),      P[j * 32 + lane],        a0);
                a1 = fmaf(__shfl_sync(0xffffffffu, v, j + 8),  P[(j + 8) * 32 + lane],  a1);
                a2 = fmaf(__shfl_sync(0xffffffffu, v, j + 16), P[(j + 16) * 32 + lane], a2);
                a3 = fmaf(__shfl_sync(0xffffffffu, v, j + 24), P[(j + 24) * 32 + lane], a3);
            }
            v = (a0 + a1) + (a2 + a3);
        }
        sv[lane] = v;
    }
    __syncthreads();

    float acc = 0.f;
    #pragma unroll
    for (int j = 0; j < BOND; ++j)
        acc = fmaf(sv[j], pr[j], acc);
    g_w[tid] = acc;
}

// ---------------------------------------------------------------------------
// Output: one warp per batch row, 8 rows per block. No smem, no barriers.
// 8 independent LDG.128 per lane (MLP=8), warp multiply-reduce, float4 stores.
// ---------------------------------------------------------------------------
__global__ __launch_bounds__(256) void mps_output_kernel(const float* __restrict__ inputs,
                                                         const float* __restrict__ bias,
                                                         float* __restrict__ out) {
    const int lane = threadIdx.x & 31;
    const int b    = blockIdx.x * 8 + (threadIdx.x >> 5);

    const float4* row = (const float4*)(inputs + (size_t)b * IDIM);
    float4 r[8];
    #pragma unroll
    for (int i = 0; i < 8; ++i) r[i] = row[lane + 32 * i];

    float p0 = (r[0].x * r[0].y) * (r[0].z * r[0].w);
    float p1 = (r[1].x * r[1].y) * (r[1].z * r[1].w);
    float p2 = (r[2].x * r[2].y) * (r[2].z * r[2].w);
    float p3 = (r[3].x * r[3].y) * (r[3].z * r[3].w);
    float p4 = (r[4].x * r[4].y) * (r[4].z * r[4].w);
    float p5 = (r[5].x * r[5].y) * (r[5].z * r[5].w);
    float p6 = (r[6].x * r[6].y) * (r[6].z * r[6].w);
    float p7 = (r[7].x * r[7].y) * (r[7].z * r[7].w);
    float p  = ((p0 * p1) * (p2 * p3)) * ((p4 * p5) * (p6 * p7));

    #pragma unroll
    for (int off = 16; off; off >>= 1)
        p *= __shfl_xor_sync(0xffffffffu, p, off);

    const float4* w4 = (const float4*)g_w;
    const float4* b4 = (const float4*)bias;
    float4*       o4 = (float4*)(out + (size_t)b * ODIM);

    #pragma unroll
    for (int i = 0; i < 4; ++i) {
        const float4 wv = w4[lane + 32 * i];
        const float4 bv = b4[lane + 32 * i];
        float4 ov;
        ov.x = fmaf(p, wv.x, bv.x);
        ov.y = fmaf(p, wv.y, bv.y);
        ov.z = fmaf(p, wv.z, bv.z);
        ov.w = fmaf(p, wv.w, bv.w);
        o4[lane + 32 * i] = ov;
    }
}

// ---------------------------------------------------------------------------
extern "C" void kernel_launch(void* const* d_in, const int* in_sizes, int n_in,
                              void* d_out, int out_size) {
    const float* inputs = (const float*)d_in[0];
    const float* cores  = (const float*)d_in[1];
    const float* proj   = (const float*)d_in[2];
    const float* bias   = (const float*)d_in[3];
    float* out = (float*)d_out;

    float* p1; cudaGetSymbolAddress((void**)&p1, g_P1);
    float* p2; cudaGetSymbolAddress((void**)&p2, g_P2);
    float* p3; cudaGetSymbolAddress((void**)&p3, g_P3);

    // Idempotent, capture-safe, called unconditionally (no static guards).
    cudaFuncSetAttribute(mps_combine_kernel,
                         cudaFuncAttributeMaxDynamicSharedMemorySize, 65536);

    mps_prod4_kernel  <<<NP1, 256>>>(cores, p1);          // 1024 -> 256
    mps_prod4_kernel  <<<NP2, 256>>>(p1, p2);             // 256  -> 64
    mps_prod4_kernel  <<<NP3, 256>>>(p2, p3);             // 64   -> 16
    mps_combine_kernel<<<1, 512, 65536>>>(proj);          // 16-chain + projection
    mps_output_kernel <<<BATCH / 8, 256>>>(inputs, bias, out);
}